// round 7
// baseline (speedup 1.0000x reference)
#include <cuda_runtime.h>
#include <stdint.h>

#define VOCAB 50257
#define SEQ   512
#define BATCH 8
#define KD    4      // NUM_DRAFTS
#define LD    8      // DRAFT_LEN
#define NROWS 256    // KD*LD*BATCH
#define LOGITS_ELEMS (BATCH * SEQ * VOCAB)
#define PREPP 4      // prep blocks per batch row
#define NSAMP 1152   // rows 0..127 -> 5 blocks, rows 128..255 -> 4 blocks
#define NPREP (BATCH * PREPP)      // 32
#define TOTALB (NSAMP + NPREP)     // 1184 = 148 * 8 exactly

// Per-sampler-block winner, plain store each launch (no reset needed)
__device__ unsigned long long g_part[NSAMP];
__device__ float g_pmax[NPREP];
__device__ float g_psum[NPREP];
__device__ unsigned int g_done;    // self-resetting completion counter

// ---- JAX partitionable threefry bits for flat index i (< 2^32):
//      (o0, o1) = threefry2x32(key=(0,42), x0=0, x1=i);  bits = o0 ^ o1
__device__ __forceinline__ uint32_t tf_bits(uint32_t i) {
    const uint32_t ks1 = 42u;
    const uint32_t ks2 = 42u ^ 0x1BD11BDAu;
    uint32_t x0 = 0u;
    uint32_t x1 = i + ks1;
#define TF_R(r) { x0 += x1; x1 = __funnelshift_l(x1, x1, (r)); x1 ^= x0; }
    TF_R(13) TF_R(15) TF_R(26) TF_R(6)
    x0 += ks1; x1 += ks2 + 1u;
    TF_R(17) TF_R(29) TF_R(16) TF_R(24)
    x0 += ks2; x1 += 2u;
    TF_R(13) TF_R(15) TF_R(26) TF_R(6)
    x1 += ks1 + 3u;
    TF_R(17) TF_R(29) TF_R(16) TF_R(24)
    x0 += ks1; x1 += ks2 + 4u;
    TF_R(13) TF_R(15) TF_R(26) TF_R(6)
    x0 += ks2; x1 += 5u;
#undef TF_R
    return x0 ^ x1;
}

// Order-preserving float -> uint32 map (total order matching IEEE < on reals)
__device__ __forceinline__ uint32_t fmap(float v) {
    uint32_t u = __float_as_uint(v);
    return (u & 0x80000000u) ? ~u : (u | 0x80000000u);
}

__global__ void __launch_bounds__(256, 8)
fused_kernel(const float* __restrict__ logits, float* __restrict__ out) {
    __shared__ float red[256];
    __shared__ unsigned long long sbest;
    __shared__ int s_last;
    __shared__ float smax_s[BATCH], ssum_s[BATCH], meanp_s[BATCH * KD];
    volatile __shared__ float s_thrf;    // best exactly-achieved val in this block

    int bid = blockIdx.x, t = threadIdx.x;

    if (bid < NSAMP) {
        // ---------------- sampler block: gumbel-argmax, two-tier screen -----------
        int r, sub, nsub;
        if (bid < 640) { r = bid / 5; sub = bid - r * 5; nsub = 5; }
        else { int q = bid - 640; r = 128 + (q >> 2); sub = q & 3; nsub = 4; }
        int b = r & 7;
        const float* __restrict__ row = logits + ((size_t)b * SEQ + (SEQ - 1)) * VOCAB;
        if (t == 0) { sbest = 0ull; s_thrf = -INFINITY; }
        __syncthreads();

        const float tiny = 1.17549435e-38f;
        const float ln2 = 0.69314718056f;
        const float C0 = 6.9325f;            // >= 10*ln2 + 1e-3 margin
        const uint32_t M0 = 0x7FE000u;       // 2^23 - 2^13  (f < 1 - 2^-10)
        unsigned long long best = 0ull;
        uint32_t base = (uint32_t)r * (uint32_t)VOCAB;
        for (int v = sub * 256 + t; v < VOCAB; v += nsub * 256) {
            uint32_t bits = tf_bits(base + (uint32_t)v);
            uint32_t m = bits >> 9;                 // 23-bit mantissa
            float lgt = row[v];
            float thr = s_thrf;
            // tier 1: if f < 1-2^-10 then gumbel <= 10*ln2; provably loses -> skip
            if (m < M0 && lgt + C0 < thr) continue;
            // tier 2: integer clz bound  g(u) <= (clz(2^23-m)-8)*ln2
            float cf = (float)(__clz(0x800000u - m) - 8);
            float bound = fmaf(cf, ln2, lgt) + 3e-5f;
            if (bound < thr) continue;
            // exact reference formula (bit-matches XLA's __nv_logf path)
            float f = __uint_as_float(m | 0x3f800000u) - 1.0f;   // [0,1)
            float u = fmaxf(tiny, f + tiny);        // JAX uniform(tiny, 1)
            float val = lgt - logf(-logf(u));
            unsigned long long pk =
                ((unsigned long long)fmap(val) << 32) |
                (unsigned long long)(0xFFFFFFFFu - (uint32_t)v);
            if (pk > best) best = pk;
            if (val > s_thrf) s_thrf = val;         // racy, always an achieved val
        }
        atomicMax(&sbest, best);
        __syncthreads();
        if (t == 0) g_part[bid] = sbest;
    } else {
        // ---------------- prep block: partial softmax stats -----------------------
        int pb = bid - NSAMP;
        int b = pb >> 2, px = pb & 3;
        const float* __restrict__ row = logits + ((size_t)b * SEQ + (SEQ - 1)) * VOCAB;
        float mx = -INFINITY;
        for (int v = px * 256 + t; v < VOCAB; v += PREPP * 256) mx = fmaxf(mx, row[v]);
        red[t] = mx; __syncthreads();
        for (int s = 128; s > 0; s >>= 1) {
            if (t < s) red[t] = fmaxf(red[t], red[t + s]);
            __syncthreads();
        }
        mx = red[0];
        __syncthreads();
        float acc = 0.0f;
        for (int v = px * 256 + t; v < VOCAB; v += PREPP * 256) acc += expf(row[v] - mx);
        red[t] = acc; __syncthreads();
        for (int s = 128; s > 0; s >>= 1) {
            if (t < s) red[t] += red[t + s];
            __syncthreads();
        }
        if (t == 0) { g_pmax[pb] = mx; g_psum[pb] = red[0]; }
    }

    // ---------------- completion: last block runs the finalize --------------------
    __threadfence();
    if (t == 0) {
        unsigned int d = atomicAdd(&g_done, 1u);
        s_last = (d == TOTALB - 1);
    }
    __syncthreads();
    if (!s_last) return;
    if (t == 0) g_done = 0;          // replay-safe reset
    __threadfence();

    // softmax stats: deterministic fixed-order combine of 4 partials per batch row
    if (t < BATCH) {
        float gm = -INFINITY;
        #pragma unroll
        for (int i = 0; i < PREPP; i++) gm = fmaxf(gm, g_pmax[t * PREPP + i]);
        float s = 0.0f;
        #pragma unroll
        for (int i = 0; i < PREPP; i++)
            s += g_psum[t * PREPP + i] * expf(g_pmax[t * PREPP + i] - gm);
        smax_s[t] = gm; ssum_s[t] = s;
    }

    int o = t;                           // output layout (b, k, l)
    int b = o >> 5, k = (o >> 3) & 3, l = o & 7;
    int rowidx = k * 64 + l * 8 + b;     // gumbel-field row (k, l, b)
    int pbase, pcnt;
    if (rowidx < 128) { pbase = rowidx * 5; pcnt = 5; }
    else { pbase = 640 + (rowidx - 128) * 4; pcnt = 4; }
    unsigned long long pk = g_part[pbase];
    for (int i = 1; i < pcnt; i++) {
        unsigned long long q = g_part[pbase + i];
        if (q > pk) pk = q;
    }
    __syncthreads();

    uint32_t tok = 0xFFFFFFFFu - (uint32_t)(pk & 0xFFFFFFFFull);
    float lg = logits[((size_t)b * SEQ + (SEQ - 1)) * VOCAB + tok];
    float prob = expf(lg - smax_s[b]) / ssum_s[b];

    out[o] = (float)tok;                               // draft_tokens
    out[NROWS + o] = prob;                             // draft_probs
    out[2 * NROWS + o] = (prob >= 0.8f) ? 1.0f : 0.0f; // accepted_mask
    red[o] = prob;
    __syncthreads();

    if (o < BATCH * KD) {                              // (b, k)
        int bb = o >> 2, kk = o & 3;
        float sp = 0.0f, sm = 0.0f;
        #pragma unroll
        for (int ll = 0; ll < LD; ll++) {
            float p = red[bb * 32 + kk * 8 + ll];
            sp += p;
            sm += (p >= 0.8f) ? 1.0f : 0.0f;
        }
        out[3 * NROWS + o] = sm / 8.0f;                // acceptance_ratio
        meanp_s[o] = sp / 8.0f;
    }
    __syncthreads();

    if (o < BATCH) {                                   // best_draft_idx (first max)
        int best = 0;
        float bv = meanp_s[o * 4];
        #pragma unroll
        for (int kk = 1; kk < KD; kk++) {
            float v2 = meanp_s[o * 4 + kk];
            if (v2 > bv) { bv = v2; best = kk; }
        }
        out[3 * NROWS + 32 + o] = (float)best;
    }
}

extern "C" void kernel_launch(void* const* d_in, const int* in_sizes, int n_in,
                              void* d_out, int out_size) {
    int li = 1;
    for (int i = 0; i < n_in; i++) {
        if (in_sizes[i] == LOGITS_ELEMS) { li = i; break; }
    }
    const float* logits = (const float*)d_in[li];
    float* out = (float*)d_out;

    fused_kernel<<<TOTALB, 256>>>(logits, out);
}